// round 15
// baseline (speedup 1.0000x reference)
#include <cuda_runtime.h>
#include <cuda_fp16.h>
#include <cstdint>

#define TT    1024
#define BB    128
#define VV    512
#define LMAX  128
#define ROWH  136            // halves per (b,t) row: [lab0..lab127, blank, pad] (272B)
#define CHUNK 48             // timesteps per cp.async tile (4 phases)
#define KSTEP 12             // real steps per barrier phase
#define HSTEP 6              // fused (2-step) iterations per phase
#define PWARP 20             // owned pairs per warp (32 - KSTEP)
#define NTHR  224            // 7 warps
#define NWARP 7
#define TEXP  100            // renorm target exponent: pin block max to ~2^100
#define LN2F  0.6931471805599453f

// Scratch (device globals — no allocation allowed)
__device__ __align__(16) __half g_lph[(size_t)BB * TT * ROWH];  // ~34 MB fp16 u-values
__device__ float g_lz[TT * BB];    // per-row log-sum-exp residual
__device__ float g_ps[BB];

__device__ __forceinline__ void cpasync16(void* smem_dst, const void* gsrc) {
    uint32_t sa = (uint32_t)__cvta_generic_to_shared(smem_dst);
    asm volatile("cp.async.cg.shared.global [%0], [%1], 16;\n" :: "r"(sa), "l"(gsrc));
}

// ---------------------------------------------------------------------------
// Kernel 1: per (t,b) row with t < act_len(b): softmax stats; store
// UNNORMALIZED probs u[c]=exp(a[c]-rowmax) as fp16 (labels at 0..127, blank
// at 128 -> aligned uint2 stores) + fp32 lz residual. Dead rows skipped.
// ---------------------------------------------------------------------------
__global__ void k_logprobs(const float* __restrict__ acts,
                           const int*   __restrict__ labels,
                           const int*   __restrict__ act_lens) {
    int gw   = (blockIdx.x * blockDim.x + threadIdx.x) >> 5;   // row id = t*BB + b
    int lane = threadIdx.x & 31;
    if (gw >= TT * BB) return;

    int b = gw & (BB - 1);
    int t = gw >> 7;
    if (t >= act_lens[b]) return;             // dead row: skip entirely

    const float* row = acts + (size_t)gw * VV;
    const float4* r4 = (const float4*)row;

    float4 a0 = r4[lane];
    float4 a1 = r4[lane + 32];
    float4 a2 = r4[lane + 64];
    float4 a3 = r4[lane + 96];

    float m = fmaxf(fmaxf(fmaxf(a0.x, a0.y), fmaxf(a0.z, a0.w)),
                    fmaxf(fmaxf(a1.x, a1.y), fmaxf(a1.z, a1.w)));
    m = fmaxf(m, fmaxf(fmaxf(a2.x, a2.y), fmaxf(a2.z, a2.w)));
    m = fmaxf(m, fmaxf(fmaxf(a3.x, a3.y), fmaxf(a3.z, a3.w)));
    #pragma unroll
    for (int o = 16; o; o >>= 1) m = fmaxf(m, __shfl_xor_sync(0xFFFFFFFFu, m, o));

    float s = __expf(a0.x - m) + __expf(a0.y - m) + __expf(a0.z - m) + __expf(a0.w - m)
            + __expf(a1.x - m) + __expf(a1.y - m) + __expf(a1.z - m) + __expf(a1.w - m)
            + __expf(a2.x - m) + __expf(a2.y - m) + __expf(a2.z - m) + __expf(a2.w - m)
            + __expf(a3.x - m) + __expf(a3.y - m) + __expf(a3.z - m) + __expf(a3.w - m);
    #pragma unroll
    for (int o = 16; o; o >>= 1) s += __shfl_xor_sync(0xFFFFFFFFu, s, o);

    __half* dst = g_lph + ((size_t)b * TT + t) * ROWH;
    int4 c4 = ((const int4*)(labels + b * LMAX))[lane];   // 4 labels per lane
    float e0 = __expf(row[c4.x] - m);
    float e1 = __expf(row[c4.y] - m);
    float e2 = __expf(row[c4.z] - m);
    float e3 = __expf(row[c4.w] - m);
    __half2 h01 = __floats2half2_rn(e0, e1);
    __half2 h23 = __floats2half2_rn(e2, e3);
    uint2 pk;
    pk.x = reinterpret_cast<uint32_t&>(h01);
    pk.y = reinterpret_cast<uint32_t&>(h23);
    ((uint2*)dst)[lane] = pk;                 // labels j = 4*lane .. 4*lane+3
    if (lane == 0) {
        dst[128] = __float2half(__expf(row[0] - m));   // blank at slot 128
        g_lz[gw] = __logf(s);                 // residual normalizer
    }
}

// ---------------------------------------------------------------------------
// Kernel 2: per-sample alpha scan in SCALED LINEAR domain, FUSED 2-STEP
// wavefront. Pair p owns s=2p (blank) and s=2p+1 (label). Two timesteps per
// iteration:
//   T1 = ae+ao[-1]; T2 = ao[-1]+ae[-1]+c[-1]*ao[-2]; T3 = ao+ae+cf*ao[-1]
//   ae'' = (T1*ub_t + T2*ul_t[p-1]) * ub_{t+1}
//   ao'' = (T3*ul_t[p] + T1*ub_t + cf*T2*ul_t[p-1]) * ul_{t+1}[p]
// Three INDEPENDENT shfls per fused step (dist 1,1,2) -> chain ~42cy/2 steps.
// Halo decays 2 lanes per fused step: 12 halo lanes = 6 fused = 12 real
// steps per phase. Lattice truncated at Lb (value predicates; loads clamped).
// Per-phase power-of-2 renorm to 2^TEXP via __reduce_max_sync; wred parity
// double-buffered. log P = log(ae_end+ao_end-1) + ln2*Ce - sum lz.
// ---------------------------------------------------------------------------
__global__ __launch_bounds__(NTHR, 1)
void k_alpha(const int* __restrict__ labels,
             const int* __restrict__ act_lens,
             const int* __restrict__ label_lens) {
    __shared__ __align__(16) __half tile[2][CHUNK][ROWH];  // 26.1 KB
    __shared__ float xae[2][132];
    __shared__ float xao[2][132];
    __shared__ float wred[2][NWARP];
    __shared__ int   lab[LMAX];

    int b   = blockIdx.x;
    int tid = threadIdx.x;
    int w   = tid >> 5;
    int l   = tid & 31;
    int p   = PWARP * w - KSTEP + l;          // pair index in [-12, 139]

    if (tid < LMAX) lab[tid] = labels[b * LMAX + tid];
    if (tid < 132) { xae[0][tid] = 0.0f; xao[0][tid] = 0.0f; }
    int len = act_lens[b];
    int Lb  = label_lens[b];                  // true label length, [64, 128]
    const __half* my = g_lph + (size_t)b * TT * ROWH;
    __syncthreads();
    if (tid == 0) {
        xae[0][0] = __half2float(my[128]);    // s=0 blank
        xao[0][0] = __half2float(my[0]);      // s=1 first label
    }

    bool haveP = (p >= 0 && p <= 128);
    bool okO   = (p >= 0 && p < Lb);
    bool okOm1 = (p >= 1 && p <= Lb);         // (p-1) < Lb
    bool ownA  = (l >= KSTEP) && (p >= 0) && (p <= 128);
    bool ownO  = (l >= KSTEP) && (p >= 0) && (p <= 127);
    int  ip    = (p >= 0 && p < 128)  ? p     : 0;   // clamped load idx for ul[p]
    int  ipm1  = (p >= 1 && p <= 128) ? p - 1 : 0;   // clamped load idx for ul[p-1]
    float cf  = ((p >= 1 && p <= 127) ? (lab[p]   != lab[p - 1]) : false) ? 1.0f : 0.0f;
    float cm1 = ((p >= 2 && p <= 128) ? (lab[p-1] != lab[p - 2]) : false) ? 1.0f : 0.0f;

    // ---- cp.async chunk prefetcher (16B = 8 halves; 17 words/row) ----
    const int NWD = CHUNK * (ROWH / 8);       // 816 words per chunk
    auto prefetch = [&](int t0, int bf) {
        for (int wd = tid; wd < NWD; wd += NTHR) {
            int tt = wd / (ROWH / 8);
            int q  = wd - tt * (ROWH / 8);
            int t  = t0 + tt;
            if (t < TT)
                cpasync16(&tile[bf][tt][q * 8], my + (size_t)t * ROWH + q * 8);
        }
        asm volatile("cp.async.commit_group;\n");
    };

    prefetch(1, 0);
    if (1 + CHUNK < len) prefetch(1 + CHUNK, 1);
    __syncthreads();

    int   par   = 0, buf = 0;
    int   Ce    = 0;         // accumulated renorm exponent: true = stored * 2^Ce
    int   pend  = 0;
    float scale = __int_as_float((127 + TEXP) << 23);   // 2^(TEXP-pend), pend=0

    for (int cs = 1; cs < len; cs += CHUNK, buf ^= 1) {
        bool more = (cs + CHUNK) < len;
        if (more) asm volatile("cp.async.wait_group 1;\n");
        else      asm volatile("cp.async.wait_group 0;\n");
        __syncthreads();                      // tile[buf] ready

        int ce = more ? (cs + CHUNK) : len;
        for (int base = cs; base < ce; base += KSTEP) {
            float a_e = haveP ? xae[par][p] * scale : 0.0f;
            float a_o = okO   ? xao[par][p] * scale : 0.0f;
            Ce += pend - TEXP;
            const __half* r0 = &tile[buf][base - cs][0];

            #pragma unroll
            for (int k = 0; k < HSTEP; k++) {
                int t0 = base + 2 * k;
                if (t0 + 1 < ce) {            // fused 2-step (uniform)
                    float aom1 = __shfl_up_sync(0xFFFFFFFFu, a_o, 1);
                    float aem1 = __shfl_up_sync(0xFFFFFFFFu, a_e, 1);
                    float aom2 = __shfl_up_sync(0xFFFFFFFFu, a_o, 2);
                    if (l == 0) { aom1 = 0.0f; aem1 = 0.0f; }
                    if (l < 2)  { aom2 = 0.0f; }
                    float ubt  = __half2float(r0[128]);
                    float ubt1 = __half2float(r0[ROWH + 128]);
                    float ult  = okO   ? __half2float(r0[ip])        : 0.0f;
                    float ultm = okOm1 ? __half2float(r0[ipm1])      : 0.0f;
                    float ult1 = okO   ? __half2float(r0[ROWH + ip]) : 0.0f;
                    float T1 = a_e + aom1;
                    float T2 = fmaf(cm1, aom2, aom1 + aem1);
                    float T3 = fmaf(cf,  aom1, a_o + a_e);
                    float U1 = T1 * ubt;
                    float V2 = T2 * ultm;
                    a_e = (U1 + V2) * ubt1;
                    a_o = fmaf(T3, ult, fmaf(cf, V2, U1)) * ult1;
                    r0 += 2 * ROWH;
                } else if (t0 < ce) {         // single trailing step (uniform)
                    float aom1 = __shfl_up_sync(0xFFFFFFFFu, a_o, 1);
                    if (l == 0) aom1 = 0.0f;
                    float ubt = __half2float(r0[128]);
                    float ult = okO ? __half2float(r0[ip]) : 0.0f;
                    float nae = (a_e + aom1) * ubt;
                    a_o = fmaf(cf, aom1, a_o + a_e) * ult;
                    a_e = nae;
                    r0 += ROWH;
                }
            }

            // per-warp max for renorm (halo lanes only underestimate; spill
            // lanes bounded by real values since u <= 1 -> cannot dominate)
            float v = fmaxf(a_e, a_o);
            unsigned mv = __reduce_max_sync(0xFFFFFFFFu, __float_as_uint(v));
            if (l == 0) wred[par][w] = __uint_as_float(mv);

            if (ownA) xae[par ^ 1][p] = a_e;
            if (ownO) xao[par ^ 1][p] = a_o;
            __syncthreads();

            float mx = fmaxf(fmaxf(fmaxf(wred[par][0], wred[par][1]),
                                   fmaxf(wred[par][2], wred[par][3])),
                             fmaxf(fmaxf(wred[par][4], wred[par][5]), wred[par][6]));
            par ^= 1;
            pend  = (__float_as_int(mx) >> 23) - 126;           // 2^pend >= mx
            scale = __int_as_float((127 + TEXP - pend) << 23);  // 2^(TEXP-pend)
        }

        int nc = cs + 2 * CHUNK;
        if (nc < len) prefetch(nc, buf);
    }

    // ---- sum of per-row normalizers lz over t < len ----
    float slz = 0.0f;
    for (int t = tid; t < len; t += NTHR) slz += g_lz[t * BB + b];
    #pragma unroll
    for (int o = 16; o; o >>= 1) slz += __shfl_xor_sync(0xFFFFFFFFu, slz, o);
    __syncthreads();
    if (l == 0) wred[0][w] = slz;
    __syncthreads();

    if (tid == 0) {
        float SLZ = wred[0][0] + wred[0][1] + wred[0][2] + wred[0][3]
                  + wred[0][4] + wred[0][5] + wred[0][6];
        float af = xae[par][Lb] + xao[par][Lb - 1];   // end = 2L -> ae[L], ao[L-1]
        g_ps[b] = -(__logf(af) + (float)Ce * LN2F - SLZ);
    }
}

// ---------------------------------------------------------------------------
// Kernel 3: deterministic mean over B=128 per-sample losses.
// ---------------------------------------------------------------------------
__global__ void k_final(float* __restrict__ out) {
    __shared__ float sh[4];
    int tid = threadIdx.x;                   // 128 threads
    float v = g_ps[tid];
    #pragma unroll
    for (int o = 16; o; o >>= 1) v += __shfl_xor_sync(0xFFFFFFFFu, v, o);
    if ((tid & 31) == 0) sh[tid >> 5] = v;
    __syncthreads();
    if (tid == 0) out[0] = (sh[0] + sh[1] + sh[2] + sh[3]) * (1.0f / (float)BB);
}

extern "C" void kernel_launch(void* const* d_in, const int* in_sizes, int n_in,
                              void* d_out, int out_size) {
    const float* acts       = (const float*)d_in[0];
    const int*   labels     = (const int*)d_in[1];
    const int*   act_lens   = (const int*)d_in[2];
    const int*   label_lens = (const int*)d_in[3];
    (void)in_sizes; (void)n_in; (void)out_size;

    k_logprobs<<<(TT * BB) / 8, 256>>>(acts, labels, act_lens);
    k_alpha<<<BB, NTHR>>>(labels, act_lens, label_lens);
    k_final<<<1, 128>>>((float*)d_out);
}

// round 16
// speedup vs baseline: 1.0778x; 1.0778x over previous
#include <cuda_runtime.h>
#include <cuda_fp16.h>
#include <cstdint>

#define TT    1024
#define BB    128
#define VV    512
#define LMAX  128
#define ROWH  136            // halves per (b,t) row: [lab0..lab127, blank, pad] (272B)
#define CHUNK 24             // timesteps per cp.async tile (2 phases)
#define KSTEP 12             // steps per barrier phase (wavefront halo depth)
#define PWARP 20             // owned pairs per warp (32 - KSTEP)
#define NTHR  224            // 7 warps
#define NWARP 7
#define TEXP  100            // renorm target exponent: pin block max to ~2^100
#define LN2F  0.6931471805599453f

// Scratch (device globals — no allocation allowed)
__device__ __align__(16) __half g_lph[(size_t)BB * TT * ROWH];  // ~34 MB fp16 u-values
__device__ float g_lz[TT * BB];    // per-row log-sum-exp residual
__device__ float g_ps[BB];

__device__ __forceinline__ void cpasync16(void* smem_dst, const void* gsrc) {
    uint32_t sa = (uint32_t)__cvta_generic_to_shared(smem_dst);
    asm volatile("cp.async.cg.shared.global [%0], [%1], 16;\n" :: "r"(sa), "l"(gsrc));
}

// ---------------------------------------------------------------------------
// Kernel 1: per (t,b) row with t < act_len(b): softmax stats; store
// UNNORMALIZED probs u[c]=exp(a[c]-rowmax) as fp16 (labels at 0..127, blank
// at 128 -> aligned uint2 stores) + fp32 lz residual. Dead rows skipped.
// ---------------------------------------------------------------------------
__global__ void k_logprobs(const float* __restrict__ acts,
                           const int*   __restrict__ labels,
                           const int*   __restrict__ act_lens) {
    int gw   = (blockIdx.x * blockDim.x + threadIdx.x) >> 5;   // row id = t*BB + b
    int lane = threadIdx.x & 31;
    if (gw >= TT * BB) return;

    int b = gw & (BB - 1);
    int t = gw >> 7;
    if (t >= act_lens[b]) return;             // dead row: skip entirely

    const float* row = acts + (size_t)gw * VV;
    const float4* r4 = (const float4*)row;

    float4 a0 = r4[lane];
    float4 a1 = r4[lane + 32];
    float4 a2 = r4[lane + 64];
    float4 a3 = r4[lane + 96];

    float m = fmaxf(fmaxf(fmaxf(a0.x, a0.y), fmaxf(a0.z, a0.w)),
                    fmaxf(fmaxf(a1.x, a1.y), fmaxf(a1.z, a1.w)));
    m = fmaxf(m, fmaxf(fmaxf(a2.x, a2.y), fmaxf(a2.z, a2.w)));
    m = fmaxf(m, fmaxf(fmaxf(a3.x, a3.y), fmaxf(a3.z, a3.w)));
    #pragma unroll
    for (int o = 16; o; o >>= 1) m = fmaxf(m, __shfl_xor_sync(0xFFFFFFFFu, m, o));

    float s = __expf(a0.x - m) + __expf(a0.y - m) + __expf(a0.z - m) + __expf(a0.w - m)
            + __expf(a1.x - m) + __expf(a1.y - m) + __expf(a1.z - m) + __expf(a1.w - m)
            + __expf(a2.x - m) + __expf(a2.y - m) + __expf(a2.z - m) + __expf(a2.w - m)
            + __expf(a3.x - m) + __expf(a3.y - m) + __expf(a3.z - m) + __expf(a3.w - m);
    #pragma unroll
    for (int o = 16; o; o >>= 1) s += __shfl_xor_sync(0xFFFFFFFFu, s, o);

    __half* dst = g_lph + ((size_t)b * TT + t) * ROWH;
    int4 c4 = ((const int4*)(labels + b * LMAX))[lane];   // 4 labels per lane
    float e0 = __expf(row[c4.x] - m);
    float e1 = __expf(row[c4.y] - m);
    float e2 = __expf(row[c4.z] - m);
    float e3 = __expf(row[c4.w] - m);
    __half2 h01 = __floats2half2_rn(e0, e1);
    __half2 h23 = __floats2half2_rn(e2, e3);
    uint2 pk;
    pk.x = reinterpret_cast<uint32_t&>(h01);
    pk.y = reinterpret_cast<uint32_t&>(h23);
    ((uint2*)dst)[lane] = pk;                 // labels j = 4*lane .. 4*lane+3
    if (lane == 0) {
        dst[128] = __float2half(__expf(row[0] - m));   // blank at slot 128
        g_lz[gw] = __logf(s);                 // residual normalizer
    }
}

// ---------------------------------------------------------------------------
// Kernel 2: per-sample alpha scan in SCALED LINEAR domain, single-step
// wavefront (proven fastest variant, R13). Pair p owns s=2p and s=2p+1:
//   ae' = (ae + ao[p-1]) * u_blank
//   ao' = (ao + ae + cf*ao[p-1]) * u_lab[p]
// One shfl_up per step, KSTEP=12 barrier-free steps per phase (7 warps,
// lanes 0..11 decaying halo, lanes 12..31 own 20 pairs). Lattice truncated
// at Lb. Per-phase power-of-2 renorm to 2^TEXP via __reduce_max_sync; wred
// parity double-buffered. KSTEP=12/TEXP=100 sits at the precision optimum:
// band below running max ~69 nats at phase end (KSTEP=16 would be ~40 and
// fail; TEXP>102 would overflow the 3^K growth bound).
// log P = log(ae_end+ao_end-1) + ln2*Ce - sum lz.
// ---------------------------------------------------------------------------
__global__ __launch_bounds__(NTHR, 1)
void k_alpha(const int* __restrict__ labels,
             const int* __restrict__ act_lens,
             const int* __restrict__ label_lens) {
    __shared__ __align__(16) __half tile[2][CHUNK][ROWH];  // 13 KB
    __shared__ float xae[2][132];
    __shared__ float xao[2][132];
    __shared__ float wred[2][NWARP];
    __shared__ int   lab[LMAX];

    int b   = blockIdx.x;
    int tid = threadIdx.x;
    int w   = tid >> 5;
    int l   = tid & 31;
    int p   = PWARP * w - KSTEP + l;          // pair index in [-12, 139]

    if (tid < LMAX) lab[tid] = labels[b * LMAX + tid];
    if (tid < 132) { xae[0][tid] = 0.0f; xao[0][tid] = 0.0f; }
    int len = act_lens[b];
    int Lb  = label_lens[b];                  // true label length, [64, 128]
    const __half* my = g_lph + (size_t)b * TT * ROWH;
    __syncthreads();
    if (tid == 0) {
        xae[0][0] = __half2float(my[128]);    // s=0 blank
        xao[0][0] = __half2float(my[0]);      // s=1 first label
    }

    bool haveP  = (p >= 0 && p <= 128);
    bool okO    = (p >= 0 && p < Lb);         // active odd positions only
    bool ownA   = (l >= KSTEP) && (p >= 0) && (p <= 128);
    bool ownO   = (l >= KSTEP) && (p >= 0) && (p <= 127);
    int  ip     = (p >= 0 && p < 128) ? p : 0;    // clamped load idx for ul[p]
    float cf    = ((p >= 1 && p <= 127) ? (lab[p] != lab[p - 1]) : false) ? 1.0f : 0.0f;

    // ---- cp.async chunk prefetcher (16B = 8 halves; 17 words/row) ----
    const int NWD = CHUNK * (ROWH / 8);       // 408 words per chunk
    auto prefetch = [&](int t0, int bf) {
        for (int wd = tid; wd < NWD; wd += NTHR) {
            int tt = wd / (ROWH / 8);
            int q  = wd - tt * (ROWH / 8);
            int t  = t0 + tt;
            if (t < TT)
                cpasync16(&tile[bf][tt][q * 8], my + (size_t)t * ROWH + q * 8);
        }
        asm volatile("cp.async.commit_group;\n");
    };

    prefetch(1, 0);
    if (1 + CHUNK < len) prefetch(1 + CHUNK, 1);
    __syncthreads();

    int   par   = 0, buf = 0;
    int   Ce    = 0;         // accumulated renorm exponent: true = stored * 2^Ce
    int   pend  = 0;
    float scale = __int_as_float((127 + TEXP) << 23);   // 2^(TEXP-pend), pend=0

    for (int cs = 1; cs < len; cs += CHUNK, buf ^= 1) {
        bool more = (cs + CHUNK) < len;
        if (more) asm volatile("cp.async.wait_group 1;\n");
        else      asm volatile("cp.async.wait_group 0;\n");
        __syncthreads();                      // tile[buf] ready

        int ce = more ? (cs + CHUNK) : len;
        for (int base = cs; base < ce; base += KSTEP) {
            float a_e = haveP ? xae[par][p] * scale : 0.0f;
            float a_o = okO   ? xao[par][p] * scale : 0.0f;
            Ce += pend - TEXP;
            const __half* r0 = &tile[buf][base - cs][0];

            #pragma unroll
            for (int k = 0; k < KSTEP; k++) {
                if (base + k >= ce) break;    // uniform across CTA
                float ub = __half2float(r0[128]);
                float ul = okO ? __half2float(r0[ip]) : 0.0f;
                float aim1 = __shfl_up_sync(0xFFFFFFFFu, a_o, 1);
                if (l == 0) aim1 = 0.0f;
                float nae = (a_e + aim1) * ub;
                a_o = fmaf(cf, aim1, a_o + a_e) * ul;
                a_e = nae;
                r0 += ROWH;
            }

            // per-warp max for renorm (halo lanes only underestimate; spill
            // lanes bounded by real values since u <= 1 -> cannot dominate)
            float v = fmaxf(a_e, a_o);
            unsigned mv = __reduce_max_sync(0xFFFFFFFFu, __float_as_uint(v));
            if (l == 0) wred[par][w] = __uint_as_float(mv);

            if (ownA) xae[par ^ 1][p] = a_e;
            if (ownO) xao[par ^ 1][p] = a_o;
            __syncthreads();

            float mx = fmaxf(fmaxf(fmaxf(wred[par][0], wred[par][1]),
                                   fmaxf(wred[par][2], wred[par][3])),
                             fmaxf(fmaxf(wred[par][4], wred[par][5]), wred[par][6]));
            par ^= 1;
            pend  = (__float_as_int(mx) >> 23) - 126;           // 2^pend >= mx
            scale = __int_as_float((127 + TEXP - pend) << 23);  // 2^(TEXP-pend)
        }

        int nc = cs + 2 * CHUNK;
        if (nc < len) prefetch(nc, buf);
    }

    // ---- sum of per-row normalizers lz over t < len ----
    float slz = 0.0f;
    for (int t = tid; t < len; t += NTHR) slz += g_lz[t * BB + b];
    #pragma unroll
    for (int o = 16; o; o >>= 1) slz += __shfl_xor_sync(0xFFFFFFFFu, slz, o);
    __syncthreads();
    if (l == 0) wred[0][w] = slz;
    __syncthreads();

    if (tid == 0) {
        float SLZ = wred[0][0] + wred[0][1] + wred[0][2] + wred[0][3]
                  + wred[0][4] + wred[0][5] + wred[0][6];
        float af = xae[par][Lb] + xao[par][Lb - 1];   // end = 2L -> ae[L], ao[L-1]
        g_ps[b] = -(__logf(af) + (float)Ce * LN2F - SLZ);
    }
}

// ---------------------------------------------------------------------------
// Kernel 3: deterministic mean over B=128 per-sample losses.
// ---------------------------------------------------------------------------
__global__ void k_final(float* __restrict__ out) {
    __shared__ float sh[4];
    int tid = threadIdx.x;                   // 128 threads
    float v = g_ps[tid];
    #pragma unroll
    for (int o = 16; o; o >>= 1) v += __shfl_xor_sync(0xFFFFFFFFu, v, o);
    if ((tid & 31) == 0) sh[tid >> 5] = v;
    __syncthreads();
    if (tid == 0) out[0] = (sh[0] + sh[1] + sh[2] + sh[3]) * (1.0f / (float)BB);
}

extern "C" void kernel_launch(void* const* d_in, const int* in_sizes, int n_in,
                              void* d_out, int out_size) {
    const float* acts       = (const float*)d_in[0];
    const int*   labels     = (const int*)d_in[1];
    const int*   act_lens   = (const int*)d_in[2];
    const int*   label_lens = (const int*)d_in[3];
    (void)in_sizes; (void)n_in; (void)out_size;

    k_logprobs<<<(TT * BB) / 8, 256>>>(acts, labels, act_lens);
    k_alpha<<<BB, NTHR>>>(labels, act_lens, label_lens);
    k_final<<<1, 128>>>((float*)d_out);
}